// round 2
// baseline (speedup 1.0000x reference)
#include <cuda_runtime.h>
#include <math.h>

#define B 4
#define N 2048
#define M 2048
#define C 512
#define H 4
#define DV 128
#define DQK 256

// scratch
__device__ __align__(16) float g_qn[B * H * N * DQK];   // 32 MB
__device__ __align__(16) float g_kn[B * H * M * DQK];   // 32 MB
__device__ __align__(16) float g_o [B * N * C];         // 16 MB

// ---------------------------------------------------------------------------
// Kernel 1: fused QKV projection + per-head L2 norm * radius.
// out[r, h*256+c] = sum_k src[r,k] * Wqkv[h*256+c, k], then per-(row,head)
// l2-normalize the 256-wide chunk and scale by radius[h].
// Tile: 64 rows x 256 cols (one full head) so the norm is block-local.
// threads 256 = 16x16; each thread: 4 rows x 16 cols (cols = tx + 16*j).
// ---------------------------------------------------------------------------
__global__ __launch_bounds__(256) void qkv_norm_kernel(
    const float* __restrict__ x, const float* __restrict__ ctx,
    const float* __restrict__ Wqkv, const float* __restrict__ radius)
{
    __shared__ float As[64 * 17];
    __shared__ float Ws[256 * 17];

    const float* src = (blockIdx.z == 0) ? x : ctx;
    float* dst = (blockIdx.z == 0) ? g_qn : g_kn;
    const int h  = blockIdx.y;
    const int r0 = blockIdx.x * 64;
    const int tid = threadIdx.x;
    const int tx = tid & 15, ty = tid >> 4;

    float acc[4][16];
#pragma unroll
    for (int i = 0; i < 4; i++)
#pragma unroll
        for (int j = 0; j < 16; j++) acc[i][j] = 0.f;

    for (int kc = 0; kc < C; kc += 16) {
#pragma unroll
        for (int t = 0; t < 4; t++) {
            int i = tid + t * 256;
            int r = i >> 4, k = i & 15;
            As[r * 17 + k] = src[(size_t)(r0 + r) * C + kc + k];
        }
#pragma unroll
        for (int t = 0; t < 16; t++) {
            int i = tid + t * 256;
            int c = i >> 4, k = i & 15;
            Ws[c * 17 + k] = Wqkv[(size_t)(h * 256 + c) * C + kc + k];
        }
        __syncthreads();
#pragma unroll
        for (int kk = 0; kk < 16; kk++) {
            float a[4], w[16];
#pragma unroll
            for (int i = 0; i < 4; i++) a[i] = As[(ty * 4 + i) * 17 + kk];
#pragma unroll
            for (int j = 0; j < 16; j++) w[j] = Ws[(tx + 16 * j) * 17 + kk];
#pragma unroll
            for (int i = 0; i < 4; i++)
#pragma unroll
                for (int j = 0; j < 16; j++) acc[i][j] += a[i] * w[j];
        }
        __syncthreads();
    }

    const float r = radius[h];
#pragma unroll
    for (int i = 0; i < 4; i++) {
        float ss = 0.f;
#pragma unroll
        for (int j = 0; j < 16; j++) ss += acc[i][j] * acc[i][j];
        // reduce across the 16 tx lanes (stays inside each 16-lane half-warp)
#pragma unroll
        for (int o = 1; o < 16; o <<= 1) ss += __shfl_xor_sync(0xffffffffu, ss, o);
        const float nrm = sqrtf(ss);
        const float sc = r / fmaxf(nrm, 1e-12f);
        const int gr = r0 + ty * 4 + i;
        const int b = gr >> 11;          // / 2048
        const int n = gr & 2047;
        float* out = dst + ((size_t)(b * H + h) * N + n) * DQK;
#pragma unroll
        for (int j = 0; j < 16; j++) out[tx + 16 * j] = acc[i][j] * sc;
    }
}

// ---------------------------------------------------------------------------
// Kernel 2: attention, one-pass softmax with static max shift.
// Block = 64 queries of one (b,h). Q tile resident in SMEM; stream K/V in
// 64-row tiles. s = q.k / sqrt(128) in [-sqrt(128), sqrt(128)] -> fixed shift.
// ---------------------------------------------------------------------------
#define SMEM_ATTN ((64 * 256 + 64 * 257 + 64 * 128 + 64 * 65) * 4)

__global__ __launch_bounds__(256) void attn_kernel(const float* __restrict__ ctx)
{
    extern __shared__ float sm[];
    float* Qs = sm;                    // 64 x 256
    float* Ks = Qs + 64 * 256;         // 64 x 257 (padded)
    float* Vs = Ks + 64 * 257;         // 64 x 128
    float* Ps = Vs + 64 * 128;         // 64 x 65 (padded)

    const int nt = blockIdx.x;
    const int h  = blockIdx.y;
    const int b  = blockIdx.z;
    const int tid = threadIdx.x;
    const int tx = tid & 15, ty = tid >> 4;

    const float* qbase = g_qn + ((size_t)(b * H + h) * N + nt * 64) * DQK;
    const float* kbase = g_kn + ((size_t)(b * H + h) * M) * DQK;
    const float* vbase = ctx + (size_t)b * M * C + h * DV;

    // load Q tile (float4)
    {
        const float4* q4 = (const float4*)qbase;
        float4* Qs4 = (float4*)Qs;
#pragma unroll
        for (int t = 0; t < 16; t++) Qs4[tid + t * 256] = q4[tid + t * 256];
    }

    float o_acc[4][8];
    float rsum[4];
#pragma unroll
    for (int i = 0; i < 4; i++) {
        rsum[i] = 0.f;
#pragma unroll
        for (int j = 0; j < 8; j++) o_acc[i][j] = 0.f;
    }

    const float SCALE = 0.08838834764831845f;  // 1/sqrt(128)
    const float SMAX  = 11.313708498984761f;   // sqrt(128)

    for (int mt = 0; mt < M / 64; mt++) {
        __syncthreads();
        // load K tile into padded smem
        {
            const float4* k4 = (const float4*)(kbase + (size_t)mt * 64 * DQK);
#pragma unroll
            for (int t = 0; t < 16; t++) {
                int i = tid + t * 256;
                float4 v = k4[i];
                int row = i >> 6;            // 64 float4 per row
                int dp = (i & 63) * 4;
                float* kd = Ks + row * 257 + dp;
                kd[0] = v.x; kd[1] = v.y; kd[2] = v.z; kd[3] = v.w;
            }
        }
        // load V tile
        {
#pragma unroll
            for (int t = 0; t < 8; t++) {
                int i = tid + t * 256;
                int row = i >> 5;            // 32 float4 per row
                int dp = (i & 31) * 4;
                float4 v = *(const float4*)(vbase + (size_t)(mt * 64 + row) * C + dp);
                *(float4*)(Vs + row * 128 + dp) = v;
            }
        }
        __syncthreads();

        // S = Q K^T  (4x4 per thread, cols = tx + 16*j)
        float s[4][4];
#pragma unroll
        for (int i = 0; i < 4; i++)
#pragma unroll
            for (int j = 0; j < 4; j++) s[i][j] = 0.f;
#pragma unroll 8
        for (int d = 0; d < DQK; d++) {
            float a[4], bb[4];
#pragma unroll
            for (int i = 0; i < 4; i++) a[i] = Qs[(ty * 4 + i) * 256 + d];
#pragma unroll
            for (int j = 0; j < 4; j++) bb[j] = Ks[(tx + 16 * j) * 257 + d];
#pragma unroll
            for (int i = 0; i < 4; i++)
#pragma unroll
                for (int j = 0; j < 4; j++) s[i][j] += a[i] * bb[j];
        }
        // p = exp(s*SCALE - SMAX); accumulate row sums; stash P
#pragma unroll
        for (int i = 0; i < 4; i++)
#pragma unroll
            for (int j = 0; j < 4; j++) {
                float p = __expf(s[i][j] * SCALE - SMAX);
                rsum[i] += p;
                Ps[(ty * 4 + i) * 65 + tx + 16 * j] = p;
            }
        __syncthreads();

        // O += P V  (4 rows x 8 cols per thread, cols = tx + 16*j)
#pragma unroll 4
        for (int mm = 0; mm < 64; mm++) {
            float p[4], v[8];
#pragma unroll
            for (int i = 0; i < 4; i++) p[i] = Ps[(ty * 4 + i) * 65 + mm];
#pragma unroll
            for (int j = 0; j < 8; j++) v[j] = Vs[mm * 128 + tx + 16 * j];
#pragma unroll
            for (int i = 0; i < 4; i++)
#pragma unroll
                for (int j = 0; j < 8; j++) o_acc[i][j] += p[i] * v[j];
        }
    }

    // full row sums across tx lanes
#pragma unroll
    for (int i = 0; i < 4; i++) {
#pragma unroll
        for (int o = 1; o < 16; o <<= 1)
            rsum[i] += __shfl_xor_sync(0xffffffffu, rsum[i], o);
    }

    // write O in reshaped layout: g_o[(b*N + n)*C + h*128 + d]
#pragma unroll
    for (int i = 0; i < 4; i++) {
        const int n = nt * 64 + ty * 4 + i;
        const float inv = 1.f / rsum[i];
        float* out = g_o + ((size_t)(b * N + n)) * C + h * DV;
#pragma unroll
        for (int j = 0; j < 8; j++) out[tx + 16 * j] = o_acc[i][j] * inv;
    }
}

// ---------------------------------------------------------------------------
// Kernel 3: output projection. out[r,o] = sum_c g_o[r,c] * Wproj[o,c]
// Tile 64 x 128; threads 256 = 16x16; 4 rows x 8 cols per thread.
// ---------------------------------------------------------------------------
__global__ __launch_bounds__(256) void proj_kernel(
    const float* __restrict__ Wproj, float* __restrict__ out)
{
    __shared__ float As[64 * 17];
    __shared__ float Ws[128 * 17];

    const int r0 = blockIdx.x * 64;
    const int c0 = blockIdx.y * 128;
    const int tid = threadIdx.x;
    const int tx = tid & 15, ty = tid >> 4;

    float acc[4][8];
#pragma unroll
    for (int i = 0; i < 4; i++)
#pragma unroll
        for (int j = 0; j < 8; j++) acc[i][j] = 0.f;

    for (int kc = 0; kc < C; kc += 16) {
#pragma unroll
        for (int t = 0; t < 4; t++) {
            int i = tid + t * 256;
            int r = i >> 4, k = i & 15;
            As[r * 17 + k] = g_o[(size_t)(r0 + r) * C + kc + k];
        }
#pragma unroll
        for (int t = 0; t < 8; t++) {
            int i = tid + t * 256;
            int c = i >> 4, k = i & 15;
            Ws[c * 17 + k] = Wproj[(size_t)(c0 + c) * C + kc + k];
        }
        __syncthreads();
#pragma unroll
        for (int kk = 0; kk < 16; kk++) {
            float a[4], w[8];
#pragma unroll
            for (int i = 0; i < 4; i++) a[i] = As[(ty * 4 + i) * 17 + kk];
#pragma unroll
            for (int j = 0; j < 8; j++) w[j] = Ws[(tx + 16 * j) * 17 + kk];
#pragma unroll
            for (int i = 0; i < 4; i++)
#pragma unroll
                for (int j = 0; j < 8; j++) acc[i][j] += a[i] * w[j];
        }
        __syncthreads();
    }

#pragma unroll
    for (int i = 0; i < 4; i++) {
        float* o = out + (size_t)(r0 + ty * 4 + i) * C + c0;
#pragma unroll
        for (int j = 0; j < 8; j++) o[tx + 16 * j] = acc[i][j];
    }
}

// ---------------------------------------------------------------------------
extern "C" void kernel_launch(void* const* d_in, const int* in_sizes, int n_in,
                              void* d_out, int out_size)
{
    const float* x      = (const float*)d_in[0];
    const float* ctx    = (const float*)d_in[1];
    const float* Wqkv   = (const float*)d_in[2];
    const float* Wproj  = (const float*)d_in[3];
    const float* radius = (const float*)d_in[4];
    float* out = (float*)d_out;

    (void)in_sizes; (void)n_in; (void)out_size;

    cudaFuncSetAttribute(attn_kernel,
                         cudaFuncAttributeMaxDynamicSharedMemorySize, SMEM_ATTN);

    // 1) QKV projection + per-head L2 norm (x -> g_qn, context -> g_kn)
    qkv_norm_kernel<<<dim3((B * N) / 64, H, 2), 256>>>(x, ctx, Wqkv, radius);

    // 2) attention per (b,h), 64-query tiles
    attn_kernel<<<dim3(N / 64, H, B), 256, SMEM_ATTN>>>(ctx);

    // 3) output projection
    proj_kernel<<<dim3((B * N) / 64, C / 128), 256>>>(Wproj, out);
}

// round 4
// speedup vs baseline: 2.5789x; 2.5789x over previous
#include <cuda_runtime.h>
#include <math.h>
#include <stdint.h>

#define B 4
#define N 2048
#define M 2048
#define C 512
#define H 4
#define DV 128
#define DQK 256

// scratch
__device__ __align__(16) float g_qn[B * H * N * DQK];   // 32 MB
__device__ __align__(16) float g_kn[B * H * M * DQK];   // 32 MB
__device__ __align__(16) float g_o [B * N * C];         // 16 MB

// ============================================================================
// tf32 mma.sync helpers (portable: sm_80+, no arch-specific 'a' features)
// ============================================================================
__device__ __forceinline__ uint32_t f2tf32(float f) {
    uint32_t u;
    asm("cvt.rna.tf32.f32 %0, %1;" : "=r"(u) : "f"(f));
    return u;
}

__device__ __forceinline__ void mma_tf32(float* c,
                                         uint32_t a0, uint32_t a1, uint32_t a2, uint32_t a3,
                                         uint32_t b0, uint32_t b1) {
    asm volatile(
        "mma.sync.aligned.m16n8k8.row.col.f32.tf32.tf32.f32 "
        "{%0,%1,%2,%3}, {%4,%5,%6,%7}, {%8,%9}, {%0,%1,%2,%3};"
        : "+f"(c[0]), "+f"(c[1]), "+f"(c[2]), "+f"(c[3])
        : "r"(a0), "r"(a1), "r"(a2), "r"(a3), "r"(b0), "r"(b1));
}

// ---------------------------------------------------------------------------
// Kernel 1: fused QKV projection + per-head L2 norm * radius, tf32 mma.
// CTA = 64 src rows x 256 out cols (one head). k = 512 streamed in 64-chunks.
// 8 warps: wr = wid&3 -> 16 rows, wc = wid>>2 -> 128 cols (16 n8-tiles).
// ---------------------------------------------------------------------------
#define QKV_XS   0                    // 64 x 68 floats
#define QKV_WS   (64 * 68)            // 256 x 68 floats
#define QKV_SS   (QKV_WS + 256 * 68)  // 2 x 64 floats
#define QKV_SMEM ((QKV_SS + 128) * 4)

__global__ __launch_bounds__(256) void qkv_mma_kernel(
    const float* __restrict__ x, const float* __restrict__ ctx,
    const float* __restrict__ Wqkv, const float* __restrict__ radius)
{
    extern __shared__ float sm[];
    uint32_t* Xu = (uint32_t*)(sm + QKV_XS);
    uint32_t* Wu = (uint32_t*)(sm + QKV_WS);
    float* ssPart = sm + QKV_SS;

    const float* src = (blockIdx.z == 0) ? x : ctx;
    float* dst = (blockIdx.z == 0) ? g_qn : g_kn;
    const int h  = blockIdx.y;
    const int r0 = blockIdx.x * 64;
    const int tid = threadIdx.x;
    const int wid = tid >> 5;
    const int lane = tid & 31;
    const int wr = wid & 3;            // m group (16 rows)
    const int wc = wid >> 2;           // n group (128 cols)
    const int qr = wr * 16 + (lane >> 2);   // this thread's row (and +8)
    const int tg = lane & 3;

    float acc[16][4];
#pragma unroll
    for (int i = 0; i < 16; i++)
#pragma unroll
        for (int j = 0; j < 4; j++) acc[i][j] = 0.f;

    for (int kc = 0; kc < 8; kc++) {
        // load X chunk: 64 x 64
#pragma unroll
        for (int t = 0; t < 4; t++) {
            int i = tid + t * 256;
            int r = i >> 4, cc = (i & 15) * 4;
            float4 v = *(const float4*)(src + (size_t)(r0 + r) * C + kc * 64 + cc);
            uint32_t* p = Xu + r * 68 + cc;
            p[0] = f2tf32(v.x); p[1] = f2tf32(v.y); p[2] = f2tf32(v.z); p[3] = f2tf32(v.w);
        }
        // load W chunk: 256 x 64
#pragma unroll
        for (int t = 0; t < 16; t++) {
            int i = tid + t * 256;
            int r = i >> 4, cc = (i & 15) * 4;
            float4 v = *(const float4*)(Wqkv + (size_t)(h * 256 + r) * C + kc * 64 + cc);
            uint32_t* p = Wu + r * 68 + cc;
            p[0] = f2tf32(v.x); p[1] = f2tf32(v.y); p[2] = f2tf32(v.z); p[3] = f2tf32(v.w);
        }
        __syncthreads();

#pragma unroll
        for (int ks = 0; ks < 8; ks++) {
            const int c = ks * 8 + tg;
            uint32_t a0 = Xu[qr * 68 + c];
            uint32_t a1 = Xu[(qr + 8) * 68 + c];
            uint32_t a2 = Xu[qr * 68 + c + 4];
            uint32_t a3 = Xu[(qr + 8) * 68 + c + 4];
#pragma unroll
            for (int nt = 0; nt < 16; nt++) {
                int n0 = wc * 128 + nt * 8 + (lane >> 2);
                uint32_t b0 = Wu[n0 * 68 + c];
                uint32_t b1 = Wu[n0 * 68 + c + 4];
                mma_tf32(acc[nt], a0, a1, a2, a3, b0, b1);
            }
        }
        __syncthreads();
    }

    // per-row sum of squares over this thread's 32 cols (x2 rows)
    float ss0 = 0.f, ss1 = 0.f;
#pragma unroll
    for (int nt = 0; nt < 16; nt++) {
        ss0 += acc[nt][0] * acc[nt][0] + acc[nt][1] * acc[nt][1];
        ss1 += acc[nt][2] * acc[nt][2] + acc[nt][3] * acc[nt][3];
    }
    // quad reduce (lanes sharing a row)
#pragma unroll
    for (int o = 1; o < 4; o <<= 1) {
        ss0 += __shfl_xor_sync(0xffffffffu, ss0, o);
        ss1 += __shfl_xor_sync(0xffffffffu, ss1, o);
    }
    if (tg == 0) {
        ssPart[wc * 64 + qr] = ss0;
        ssPart[wc * 64 + qr + 8] = ss1;
    }
    __syncthreads();

    const float rad = radius[h];
    const float sc0 = rad / fmaxf(sqrtf(ssPart[qr] + ssPart[64 + qr]), 1e-12f);
    const float sc1 = rad / fmaxf(sqrtf(ssPart[qr + 8] + ssPart[64 + qr + 8]), 1e-12f);

    {
        const int gr0 = r0 + qr;
        const int b0i = gr0 >> 11, n0i = gr0 & 2047;
        const int gr1 = gr0 + 8;
        const int b1i = gr1 >> 11, n1i = gr1 & 2047;
        float* o0 = dst + ((size_t)(b0i * H + h) * N + n0i) * DQK;
        float* o1 = dst + ((size_t)(b1i * H + h) * N + n1i) * DQK;
#pragma unroll
        for (int nt = 0; nt < 16; nt++) {
            const int col = wc * 128 + nt * 8 + 2 * tg;
            float2 v0 = make_float2(acc[nt][0] * sc0, acc[nt][1] * sc0);
            float2 v1 = make_float2(acc[nt][2] * sc1, acc[nt][3] * sc1);
            *(float2*)(o0 + col) = v0;
            *(float2*)(o1 + col) = v1;
        }
    }
}

// ---------------------------------------------------------------------------
// Kernel 2: attention via tf32 mma.sync, one-pass softmax (static shift).
// CTA = 64 queries of one (b,h). Stream 64-key tiles.
// S phase: 8 warps 4x2 (16 rows x 32 cols). PV phase: 4x2 (16 rows x 64 cols).
// ---------------------------------------------------------------------------
#define ATT_QS   0                          // 64 x 260
#define ATT_KS   (64 * 260)                 // 64 x 260
#define ATT_VS   (ATT_KS + 64 * 260)        // 64 x 136
#define ATT_PS   (ATT_VS + 64 * 136)        // 64 x 68
#define ATT_RS   (ATT_PS + 64 * 68)         // 2 x 64
#define ATT_SMEM ((ATT_RS + 128) * 4)

__global__ __launch_bounds__(256) void attn_mma_kernel(const float* __restrict__ ctx)
{
    extern __shared__ float sm[];
    uint32_t* Qu = (uint32_t*)(sm + ATT_QS);
    uint32_t* Ku = (uint32_t*)(sm + ATT_KS);
    uint32_t* Vu = (uint32_t*)(sm + ATT_VS);
    uint32_t* Pu = (uint32_t*)(sm + ATT_PS);
    float* rsPart = sm + ATT_RS;

    const int nt_blk = blockIdx.x;
    const int h  = blockIdx.y;
    const int b  = blockIdx.z;
    const int tid = threadIdx.x;
    const int wid = tid >> 5;
    const int lane = tid & 31;
    const int wr = wid & 3;
    const int wc = wid >> 2;
    const int qr = wr * 16 + (lane >> 2);
    const int tg = lane & 3;

    const float* qbase = g_qn + ((size_t)(b * H + h) * N + nt_blk * 64) * DQK;
    const float* kbase = g_kn + ((size_t)(b * H + h) * M) * DQK;
    const float* vbase = ctx + (size_t)b * M * C + h * DV;

    // Q tile -> smem (tf32)
#pragma unroll
    for (int t = 0; t < 16; t++) {
        int i = tid + t * 256;
        int r = i >> 6, cc = (i & 63) * 4;
        float4 v = *(const float4*)(qbase + (size_t)r * DQK + cc);
        uint32_t* p = Qu + r * 260 + cc;
        p[0] = f2tf32(v.x); p[1] = f2tf32(v.y); p[2] = f2tf32(v.z); p[3] = f2tf32(v.w);
    }

    float o_acc[8][4];
#pragma unroll
    for (int i = 0; i < 8; i++)
#pragma unroll
        for (int j = 0; j < 4; j++) o_acc[i][j] = 0.f;
    float rsum0 = 0.f, rsum1 = 0.f;

    const float SCALE = 0.08838834764831845f;  // 1/sqrt(128)
    const float SMAX  = 11.313708498984761f;   // sqrt(128)

    for (int mt = 0; mt < M / 64; mt++) {
        // load K tile 64 x 256
#pragma unroll
        for (int t = 0; t < 16; t++) {
            int i = tid + t * 256;
            int r = i >> 6, cc = (i & 63) * 4;
            float4 v = *(const float4*)(kbase + (size_t)(mt * 64 + r) * DQK + cc);
            uint32_t* p = Ku + r * 260 + cc;
            p[0] = f2tf32(v.x); p[1] = f2tf32(v.y); p[2] = f2tf32(v.z); p[3] = f2tf32(v.w);
        }
        // load V tile 64 x 128
#pragma unroll
        for (int t = 0; t < 8; t++) {
            int i = tid + t * 256;
            int r = i >> 5, cc = (i & 31) * 4;
            float4 v = *(const float4*)(vbase + (size_t)(mt * 64 + r) * C + cc);
            uint32_t* p = Vu + r * 136 + cc;
            p[0] = f2tf32(v.x); p[1] = f2tf32(v.y); p[2] = f2tf32(v.z); p[3] = f2tf32(v.w);
        }
        __syncthreads();

        // ---- S = Q K^T : warp tile 16 rows x 32 cols, k = 256 ----
        float s[4][4];
#pragma unroll
        for (int i = 0; i < 4; i++)
#pragma unroll
            for (int j = 0; j < 4; j++) s[i][j] = 0.f;
#pragma unroll
        for (int ks = 0; ks < 32; ks++) {
            const int c = ks * 8 + tg;
            uint32_t a0 = Qu[qr * 260 + c];
            uint32_t a1 = Qu[(qr + 8) * 260 + c];
            uint32_t a2 = Qu[qr * 260 + c + 4];
            uint32_t a3 = Qu[(qr + 8) * 260 + c + 4];
#pragma unroll
            for (int nt = 0; nt < 4; nt++) {
                int n0 = wc * 32 + nt * 8 + (lane >> 2);
                uint32_t b0 = Ku[n0 * 260 + c];
                uint32_t b1 = Ku[n0 * 260 + c + 4];
                mma_tf32(s[nt], a0, a1, a2, a3, b0, b1);
            }
        }

        // ---- softmax epilogue -> P (tf32) in smem ----
#pragma unroll
        for (int nt = 0; nt < 4; nt++) {
            float p0 = __expf(fmaf(s[nt][0], SCALE, -SMAX));
            float p1 = __expf(fmaf(s[nt][1], SCALE, -SMAX));
            float p2 = __expf(fmaf(s[nt][2], SCALE, -SMAX));
            float p3 = __expf(fmaf(s[nt][3], SCALE, -SMAX));
            rsum0 += p0 + p1;
            rsum1 += p2 + p3;
            const int col = wc * 32 + nt * 8 + 2 * tg;
            uint2 w0 = make_uint2(f2tf32(p0), f2tf32(p1));
            uint2 w1 = make_uint2(f2tf32(p2), f2tf32(p3));
            *(uint2*)(Pu + qr * 68 + col) = w0;
            *(uint2*)(Pu + (qr + 8) * 68 + col) = w1;
        }
        __syncthreads();

        // ---- O += P V : warp tile 16 rows x 64 cols, k = 64 ----
#pragma unroll
        for (int ks = 0; ks < 8; ks++) {
            const int c = ks * 8 + tg;
            uint32_t a0 = Pu[qr * 68 + c];
            uint32_t a1 = Pu[(qr + 8) * 68 + c];
            uint32_t a2 = Pu[qr * 68 + c + 4];
            uint32_t a3 = Pu[(qr + 8) * 68 + c + 4];
#pragma unroll
            for (int nt = 0; nt < 8; nt++) {
                int n0 = wc * 64 + nt * 8 + (lane >> 2);
                uint32_t b0 = Vu[c * 136 + n0];            // row k = c
                uint32_t b1 = Vu[(c + 4) * 136 + n0];      // row k = c+4
                mma_tf32(o_acc[nt], a0, a1, a2, a3, b0, b1);
            }
        }
        __syncthreads();
    }

    // ---- row-sum reduction: quad, then across the two wc halves ----
#pragma unroll
    for (int o = 1; o < 4; o <<= 1) {
        rsum0 += __shfl_xor_sync(0xffffffffu, rsum0, o);
        rsum1 += __shfl_xor_sync(0xffffffffu, rsum1, o);
    }
    if (tg == 0) {
        rsPart[wc * 64 + qr] = rsum0;
        rsPart[wc * 64 + qr + 8] = rsum1;
    }
    __syncthreads();
    const float inv0 = 1.f / (rsPart[qr] + rsPart[64 + qr]);
    const float inv1 = 1.f / (rsPart[qr + 8] + rsPart[64 + qr + 8]);

    // ---- write O ----
    {
        const int n0g = nt_blk * 64 + qr;
        float* o0 = g_o + ((size_t)(b * N + n0g)) * C + h * DV;
        float* o1 = g_o + ((size_t)(b * N + n0g + 8)) * C + h * DV;
#pragma unroll
        for (int nt = 0; nt < 8; nt++) {
            const int col = wc * 64 + nt * 8 + 2 * tg;
            *(float2*)(o0 + col) = make_float2(o_acc[nt][0] * inv0, o_acc[nt][1] * inv0);
            *(float2*)(o1 + col) = make_float2(o_acc[nt][2] * inv1, o_acc[nt][3] * inv1);
        }
    }
}

// ---------------------------------------------------------------------------
// Kernel 3: output projection (fp32, unchanged)
// ---------------------------------------------------------------------------
__global__ __launch_bounds__(256) void proj_kernel(
    const float* __restrict__ Wproj, float* __restrict__ out)
{
    __shared__ float As[64 * 17];
    __shared__ float Ws2[128 * 17];

    const int r0 = blockIdx.x * 64;
    const int c0 = blockIdx.y * 128;
    const int tid = threadIdx.x;
    const int tx = tid & 15, ty = tid >> 4;

    float acc[4][8];
#pragma unroll
    for (int i = 0; i < 4; i++)
#pragma unroll
        for (int j = 0; j < 8; j++) acc[i][j] = 0.f;

    for (int kc = 0; kc < C; kc += 16) {
#pragma unroll
        for (int t = 0; t < 4; t++) {
            int i = tid + t * 256;
            int r = i >> 4, k = i & 15;
            As[r * 17 + k] = g_o[(size_t)(r0 + r) * C + kc + k];
        }
#pragma unroll
        for (int t = 0; t < 8; t++) {
            int i = tid + t * 256;
            int c = i >> 4, k = i & 15;
            Ws2[c * 17 + k] = Wproj[(size_t)(c0 + c) * C + kc + k];
        }
        __syncthreads();
#pragma unroll
        for (int kk = 0; kk < 16; kk++) {
            float a[4], w[8];
#pragma unroll
            for (int i = 0; i < 4; i++) a[i] = As[(ty * 4 + i) * 17 + kk];
#pragma unroll
            for (int j = 0; j < 8; j++) w[j] = Ws2[(tx + 16 * j) * 17 + kk];
#pragma unroll
            for (int i = 0; i < 4; i++)
#pragma unroll
                for (int j = 0; j < 8; j++) acc[i][j] += a[i] * w[j];
        }
        __syncthreads();
    }

#pragma unroll
    for (int i = 0; i < 4; i++) {
        float* o = out + (size_t)(r0 + ty * 4 + i) * C + c0;
#pragma unroll
        for (int j = 0; j < 8; j++) o[tx + 16 * j] = acc[i][j];
    }
}

// ---------------------------------------------------------------------------
extern "C" void kernel_launch(void* const* d_in, const int* in_sizes, int n_in,
                              void* d_out, int out_size)
{
    const float* x      = (const float*)d_in[0];
    const float* ctx    = (const float*)d_in[1];
    const float* Wqkv   = (const float*)d_in[2];
    const float* Wproj  = (const float*)d_in[3];
    const float* radius = (const float*)d_in[4];
    float* out = (float*)d_out;

    (void)in_sizes; (void)n_in; (void)out_size;

    cudaFuncSetAttribute(qkv_mma_kernel,
                         cudaFuncAttributeMaxDynamicSharedMemorySize, QKV_SMEM);
    cudaFuncSetAttribute(attn_mma_kernel,
                         cudaFuncAttributeMaxDynamicSharedMemorySize, ATT_SMEM);

    // 1) QKV projection + per-head L2 norm (x -> g_qn, context -> g_kn)
    qkv_mma_kernel<<<dim3((B * N) / 64, H, 2), 256, QKV_SMEM>>>(x, ctx, Wqkv, radius);

    // 2) attention per (b,h), 64-query tiles, tf32 mma.sync
    attn_mma_kernel<<<dim3(N / 64, H, B), 256, ATT_SMEM>>>(ctx);

    // 3) output projection (fp32)
    proj_kernel<<<dim3((B * N) / 64, C / 128), 256>>>(Wproj, out);
}